// round 15
// baseline (speedup 1.0000x reference)
#include <cuda_runtime.h>
#include <cuda_bf16.h>

#define N_NODES 100000
#define E_EDGES 800000
#define H_HEADS 12
#define D_DIM 96
#define LRELU_SLOPE 0.2f
#define SLOTS 64            // per-node bucket capacity (P(deg>64) ~ 1e-40)

// ---------------- scratch ------------------------------------------------------
__device__ int      g_cnt[N_NODES];            // in-degree / cursor
__device__ int      g_srcs[N_NODES * SLOTS];   // bucketed source ids
__device__ float    g_ssrc[N_NODES * 12];      // per-(node,head) source scores
__device__ float    g_strg[N_NODES * 12];      // per-(node,head) target scores
__device__ uint4    g_normbf[N_NODES * 12];    // normalized rows, bf16x2 words [N][48]
__device__ unsigned g_wbf[96 * 48];            // W as bf16x2 words
__device__ int      g_is64;

// ---------------- setup: zero counters + dtype detect ----------------------------
__global__ void setup_kernel(const int* __restrict__ ei32) {
    int i = blockIdx.x * blockDim.x + threadIdx.x;
    if (i < N_NODES) g_cnt[i] = 0;
    if (i == 0) {
        int allz = 1;
        #pragma unroll
        for (int k = 1; k < 128; k += 2) allz &= (ei32[k] == 0);
        g_is64 = allz;
    }
}

// ---------------- wconv: one-time fp32 -> bf16 conversion of W -------------------
__global__ void wconv_kernel(const float* __restrict__ wproj) {
    int i = blockIdx.x * blockDim.x + threadIdx.x;
    if (i >= 96 * 48) return;
    float2 v = *reinterpret_cast<const float2*>(&wproj[i * 2]);
    __nv_bfloat162 bv = __float22bfloat162_rn(v);
    g_wbf[i] = *reinterpret_cast<unsigned*>(&bv);
}

// ---------------- node scores: ssrc/strg per (node, head) ------------------------
__global__ void node_score_kernel(const float* __restrict__ x,
                                  const float* __restrict__ a_src,
                                  const float* __restrict__ a_trg) {
    int idx = blockIdx.x * blockDim.x + threadIdx.x;   // n*12 + h
    if (idx >= N_NODES * 12) return;
    int h = idx % 12;

    const float4* xp = reinterpret_cast<const float4*>(x) + idx * 2;
    float4 xa = xp[0], xb = xp[1];
    const float4* sa = reinterpret_cast<const float4*>(a_src) + h * 2;
    const float4* ta = reinterpret_cast<const float4*>(a_trg) + h * 2;
    float4 s0 = sa[0], s1 = sa[1], t0 = ta[0], t1 = ta[1];

    g_ssrc[idx] = xa.x*s0.x + xa.y*s0.y + xa.z*s0.z + xa.w*s0.w
                + xb.x*s1.x + xb.y*s1.y + xb.z*s1.z + xb.w*s1.w;
    g_strg[idx] = xa.x*t0.x + xa.y*t0.y + xa.z*t0.z + xa.w*t0.w
                + xb.x*t1.x + xb.y*t1.y + xb.z*t1.z + xb.w*t1.w;
}

// ---------------- place: count + scatter fused -----------------------------------
__global__ void place_kernel(const void* __restrict__ ei) {
    int e = blockIdx.x * blockDim.x + threadIdx.x;
    if (e >= E_EDGES) return;
    int src, trg;
    if (g_is64) {
        const long long* p = (const long long*)ei;
        src = (int)p[e];
        trg = (int)p[E_EDGES + e];
    } else {
        const int* p = (const int*)ei;
        src = p[e];
        trg = p[E_EDGES + e];
    }
    int pos = atomicAdd(&g_cnt[trg], 1);
    if (pos < SLOTS) g_srcs[trg * SLOTS + pos] = src;
}

// ---------------- fused agg: exp+agg+normalize+RMS+ln -> bf16 --------------------
// 16 lanes per node (12 active, one per head). Scores precomputed -> inner loop
// is 1 LDG.32 + 2 LDG.128 + exp + 9 FMA per edge (~half the issued instrs).
__global__ __launch_bounds__(256) void agg_norm_kernel(
        const float4* __restrict__ x4,
        const float*  __restrict__ lnw) {
    int gid = blockIdx.x * 256 + threadIdx.x;   // n*16 + h
    int n = gid >> 4;
    int h = gid & 15;
    bool act = (h < 12);

    float strg = 0.0f;
    int deg = 0;
    if (act) {
        strg = g_strg[n * 12 + h];
        deg = min(g_cnt[n], SLOTS);
    }
    const int* lst = &g_srcs[n * SLOTS];

    float4 a = make_float4(0.f, 0.f, 0.f, 0.f);
    float4 b = make_float4(0.f, 0.f, 0.f, 0.f);
    float  d = 0.f;

    int i = 0;
    for (; i + 2 <= deg; i += 2) {
        int2 sp = *reinterpret_cast<const int2*>(&lst[i]);
        float s0 = g_ssrc[sp.x * 12 + h];
        float s1 = g_ssrc[sp.y * 12 + h];
        float4 xa0 = x4[sp.x * 24 + h * 2];
        float4 xb0 = x4[sp.x * 24 + h * 2 + 1];
        float4 xa1 = x4[sp.y * 24 + h * 2];
        float4 xb1 = x4[sp.y * 24 + h * 2 + 1];

        float sc0 = strg + s0;
        float sc1 = strg + s1;
        sc0 = (sc0 >= 0.f) ? sc0 : LRELU_SLOPE * sc0;
        sc1 = (sc1 >= 0.f) ? sc1 : LRELU_SLOPE * sc1;
        float w0 = __expf(sc0);
        float w1 = __expf(sc1);

        d += w0 + w1;
        a.x += w0 * xa0.x + w1 * xa1.x;
        a.y += w0 * xa0.y + w1 * xa1.y;
        a.z += w0 * xa0.z + w1 * xa1.z;
        a.w += w0 * xa0.w + w1 * xa1.w;
        b.x += w0 * xb0.x + w1 * xb1.x;
        b.y += w0 * xb0.y + w1 * xb1.y;
        b.z += w0 * xb0.z + w1 * xb1.z;
        b.w += w0 * xb0.w + w1 * xb1.w;
    }
    if (i < deg) {
        int s = lst[i];
        float sc0 = strg + g_ssrc[s * 12 + h];
        float4 xa0 = x4[s * 24 + h * 2];
        float4 xb0 = x4[s * 24 + h * 2 + 1];
        sc0 = (sc0 >= 0.f) ? sc0 : LRELU_SLOPE * sc0;
        float w0 = __expf(sc0);
        d += w0;
        a.x += w0 * xa0.x; a.y += w0 * xa0.y; a.z += w0 * xa0.z; a.w += w0 * xa0.w;
        b.x += w0 * xb0.x; b.y += w0 * xb0.y; b.z += w0 * xb0.z; b.w += w0 * xb0.w;
    }

    float r = __fdividef(1.0f, d + 1e-16f);
    a.x *= r; a.y *= r; a.z *= r; a.w *= r;
    b.x *= r; b.y *= r; b.z *= r; b.w *= r;

    float ss = act ? (a.x*a.x + a.y*a.y + a.z*a.z + a.w*a.w +
                      b.x*b.x + b.y*b.y + b.z*b.z + b.w*b.w) : 0.0f;
    ss += __shfl_xor_sync(0xffffffffu, ss, 8);
    ss += __shfl_xor_sync(0xffffffffu, ss, 4);
    ss += __shfl_xor_sync(0xffffffffu, ss, 2);
    ss += __shfl_xor_sync(0xffffffffu, ss, 1);
    float rms = rsqrtf(ss * (1.0f / 96.0f) + 1e-6f);

    if (act) {
        float4 l0 = reinterpret_cast<const float4*>(lnw)[h * 2];
        float4 l1 = reinterpret_cast<const float4*>(lnw)[h * 2 + 1];
        __nv_bfloat162 w0 = __float22bfloat162_rn(
            make_float2(a.x*rms*l0.x, a.y*rms*l0.y));
        __nv_bfloat162 w1 = __float22bfloat162_rn(
            make_float2(a.z*rms*l0.z, a.w*rms*l0.w));
        __nv_bfloat162 w2 = __float22bfloat162_rn(
            make_float2(b.x*rms*l1.x, b.y*rms*l1.y));
        __nv_bfloat162 w3 = __float22bfloat162_rn(
            make_float2(b.z*rms*l1.z, b.w*rms*l1.w));
        uint4 o;
        o.x = *reinterpret_cast<unsigned*>(&w0);
        o.y = *reinterpret_cast<unsigned*>(&w1);
        o.z = *reinterpret_cast<unsigned*>(&w2);
        o.w = *reinterpret_cast<unsigned*>(&w3);
        g_normbf[n * 12 + h] = o;
    }
}

// ---------------- GEMM via bf16 mma m16n8k16, packed 64-bit fragments ------------
#define PADW 28
#define GEMM_SMEM ((96 + 128) * PADW * 8)
__global__ __launch_bounds__(256) void gemm_mma_kernel(
        const float* __restrict__ x,
        float* __restrict__ out) {
    extern __shared__ uint2 smem2[];
    uint2* Wsm2 = smem2;                  // [96][28]
    uint2* Nsm2 = smem2 + 96 * PADW;      // [128][28]
    unsigned* Wsw = reinterpret_cast<unsigned*>(Wsm2);
    unsigned* Nsw = reinterpret_cast<unsigned*>(Nsm2);

    int tid = threadIdx.x;
    int node0 = blockIdx.x * 128;

    const uint4* wbf4 = reinterpret_cast<const uint4*>(g_wbf);
    for (int i = tid; i < 96 * 12; i += 256) {
        int row = i / 12, j = i - row * 12;
        uint4 v = wbf4[i];
        int ks = j >> 1, half = j & 1;
        int base = (row * PADW + ks * 4) * 2 + half;
        Wsw[base]     = v.x;
        Wsw[base + 2] = v.y;
        Wsw[base + 4] = v.z;
        Wsw[base + 6] = v.w;
    }
    for (int i = tid; i < 128 * 12; i += 256) {
        int mm = i / 12, j = i - mm * 12;
        int node = node0 + mm;
        uint4 v = (node < N_NODES) ? g_normbf[node * 12 + j]
                                   : make_uint4(0u, 0u, 0u, 0u);
        int ks = j >> 1, half = j & 1;
        int base = (mm * PADW + ks * 4) * 2 + half;
        Nsw[base]     = v.x;
        Nsw[base + 2] = v.y;
        Nsw[base + 4] = v.z;
        Nsw[base + 6] = v.w;
    }
    __syncthreads();

    int warp = tid >> 5, lane = tid & 31;
    int m0  = warp * 16;
    int row = lane >> 2;
    int qk  = lane & 3;

    float acc[12][4];
    #pragma unroll
    for (int nt = 0; nt < 12; nt++)
        #pragma unroll
        for (int c = 0; c < 4; c++) acc[nt][c] = 0.0f;

    #pragma unroll
    for (int ks = 0; ks < 6; ks++) {
        uint2 pa0 = Nsm2[(m0 + row)     * PADW + ks * 4 + qk];
        uint2 pa1 = Nsm2[(m0 + row + 8) * PADW + ks * 4 + qk];
        #pragma unroll
        for (int nt = 0; nt < 12; nt++) {
            uint2 pb = Wsm2[(nt * 8 + row) * PADW + ks * 4 + qk];
            asm volatile(
                "mma.sync.aligned.m16n8k16.row.col.f32.bf16.bf16.f32 "
                "{%0,%1,%2,%3}, {%4,%5,%6,%7}, {%8,%9}, {%0,%1,%2,%3};"
                : "+f"(acc[nt][0]), "+f"(acc[nt][1]),
                  "+f"(acc[nt][2]), "+f"(acc[nt][3])
                : "r"(pa0.x), "r"(pa1.x), "r"(pa0.y), "r"(pa1.y),
                  "r"(pb.x), "r"(pb.y));
        }
    }

    int nodeA = node0 + m0 + row;
    int nodeB = nodeA + 8;
    #pragma unroll
    for (int nt = 0; nt < 12; nt++) {
        int col = nt * 8 + qk * 2;
        if (nodeA < N_NODES) {
            float2 xv = *reinterpret_cast<const float2*>(&x[nodeA * 96 + col]);
            float2 ov = make_float2(xv.x + acc[nt][0], xv.y + acc[nt][1]);
            *reinterpret_cast<float2*>(&out[nodeA * 96 + col]) = ov;
        }
        if (nodeB < N_NODES) {
            float2 xv = *reinterpret_cast<const float2*>(&x[nodeB * 96 + col]);
            float2 ov = make_float2(xv.x + acc[nt][2], xv.y + acc[nt][3]);
            *reinterpret_cast<float2*>(&out[nodeB * 96 + col]) = ov;
        }
    }
}

// ---------------- launch -----------------------------------------------------------
extern "C" void kernel_launch(void* const* d_in, const int* in_sizes, int n_in,
                              void* d_out, int out_size) {
    const float* x   = (const float*)d_in[0];
    const void*  ei  = d_in[1];
    const float* w   = (const float*)d_in[2];
    const float* ss  = (const float*)d_in[3];
    const float* st  = (const float*)d_in[4];
    const float* lnw = (const float*)d_in[5];
    float*       out = (float*)d_out;

    static bool attr_set = false;
    if (!attr_set) {
        cudaFuncSetAttribute(gemm_mma_kernel,
                             cudaFuncAttributeMaxDynamicSharedMemorySize,
                             GEMM_SMEM);
        attr_set = true;
    }

    setup_kernel<<<(N_NODES + 255) / 256, 256>>>((const int*)ei);
    wconv_kernel<<<(96 * 48 + 255) / 256, 256>>>(w);
    node_score_kernel<<<(N_NODES * 12 + 255) / 256, 256>>>(x, ss, st);
    place_kernel<<<(E_EDGES + 255) / 256, 256>>>(ei);
    agg_norm_kernel<<<(N_NODES * 16) / 256, 256>>>(
        reinterpret_cast<const float4*>(x), lnw);
    gemm_mma_kernel<<<(N_NODES + 127) / 128, 256, GEMM_SMEM>>>(x, out);
}

// round 16
// speedup vs baseline: 1.0584x; 1.0584x over previous
#include <cuda_runtime.h>
#include <cuda_bf16.h>

#define N_NODES 100000
#define E_EDGES 800000
#define H_HEADS 12
#define D_DIM 96
#define LRELU_SLOPE 0.2f
#define SLOTS 64            // per-node bucket capacity (P(deg>64) ~ 1e-40)

// ---------------- scratch ------------------------------------------------------
__device__ int      g_cnt[N_NODES];            // in-degree / cursor
__device__ int      g_srcs[N_NODES * SLOTS];   // bucketed source ids
__device__ uint4    g_xbf[N_NODES * 12];       // x rows as bf16x2 words [N][48]
__device__ uint4    g_normbf[N_NODES * 12];    // normalized rows, bf16x2 words
__device__ unsigned g_wbf[96 * 48];            // W as bf16x2 words
__device__ int      g_is64;

// bf16x2 unpack: elem0 = low half (<<16), elem1 = high half (mask) — ALU-pipe ops
#define BFLO(u) __uint_as_float((u) << 16)
#define BFHI(u) __uint_as_float((u) & 0xffff0000u)

// ---------------- xconv: x -> bf16 rows; also zero cnt + dtype detect ------------
__global__ void xconv_kernel(const float4* __restrict__ x4,
                             const int* __restrict__ ei32) {
    int idx = blockIdx.x * blockDim.x + threadIdx.x;   // n*12 + h
    if (idx < N_NODES) g_cnt[idx] = 0;
    if (idx == 0) {
        int allz = 1;
        #pragma unroll
        for (int k = 1; k < 128; k += 2) allz &= (ei32[k] == 0);
        g_is64 = allz;
    }
    if (idx >= N_NODES * 12) return;
    float4 xa = x4[idx * 2];
    float4 xb = x4[idx * 2 + 1];
    __nv_bfloat162 b0 = __float22bfloat162_rn(make_float2(xa.x, xa.y));
    __nv_bfloat162 b1 = __float22bfloat162_rn(make_float2(xa.z, xa.w));
    __nv_bfloat162 b2 = __float22bfloat162_rn(make_float2(xb.x, xb.y));
    __nv_bfloat162 b3 = __float22bfloat162_rn(make_float2(xb.z, xb.w));
    uint4 o;
    o.x = *reinterpret_cast<unsigned*>(&b0);
    o.y = *reinterpret_cast<unsigned*>(&b1);
    o.z = *reinterpret_cast<unsigned*>(&b2);
    o.w = *reinterpret_cast<unsigned*>(&b3);
    g_xbf[idx] = o;
}

// ---------------- wconv: one-time fp32 -> bf16 conversion of W -------------------
__global__ void wconv_kernel(const float* __restrict__ wproj) {
    int i = blockIdx.x * blockDim.x + threadIdx.x;
    if (i >= 96 * 48) return;
    float2 v = *reinterpret_cast<const float2*>(&wproj[i * 2]);
    __nv_bfloat162 bv = __float22bfloat162_rn(v);
    g_wbf[i] = *reinterpret_cast<unsigned*>(&bv);
}

// ---------------- place: count + scatter fused -----------------------------------
__global__ void place_kernel(const void* __restrict__ ei) {
    int e = blockIdx.x * blockDim.x + threadIdx.x;
    if (e >= E_EDGES) return;
    int src, trg;
    if (g_is64) {
        const long long* p = (const long long*)ei;
        src = (int)p[e];
        trg = (int)p[E_EDGES + e];
    } else {
        const int* p = (const int*)ei;
        src = p[e];
        trg = p[E_EDGES + e];
    }
    int pos = atomicAdd(&g_cnt[trg], 1);
    if (pos < SLOTS) g_srcs[trg * SLOTS + pos] = src;
}

// ---------------- fused agg: score+exp+agg+normalize+RMS+ln (bf16 gathers) -------
// 16 lanes per node (12 active, one per head). Per edge: ONE LDG.128 (bf16 row
// chunk), ALU-pipe unpack, inline fp32 score, exp, fp32 accumulate.
__global__ __launch_bounds__(256) void agg_norm_kernel(
        const float4* __restrict__ x4,
        const float*  __restrict__ a_src,
        const float*  __restrict__ a_trg,
        const float*  __restrict__ lnw) {
    int gid = blockIdx.x * 256 + threadIdx.x;   // n*16 + h
    int n = gid >> 4;
    int h = gid & 15;
    bool act = (h < 12);

    float4 as0, as1;
    float strg = 0.0f;
    int deg = 0;
    if (act) {
        as0 = reinterpret_cast<const float4*>(a_src)[h * 2];
        as1 = reinterpret_cast<const float4*>(a_src)[h * 2 + 1];
        float4 at0 = reinterpret_cast<const float4*>(a_trg)[h * 2];
        float4 at1 = reinterpret_cast<const float4*>(a_trg)[h * 2 + 1];
        float4 xn0 = x4[(n * 12 + h) * 2];       // exact fp32 strg
        float4 xn1 = x4[(n * 12 + h) * 2 + 1];
        strg = xn0.x*at0.x + xn0.y*at0.y + xn0.z*at0.z + xn0.w*at0.w
             + xn1.x*at1.x + xn1.y*at1.y + xn1.z*at1.z + xn1.w*at1.w;
        deg = min(g_cnt[n], SLOTS);
    }
    const int* lst = &g_srcs[n * SLOTS];

    float4 a = make_float4(0.f, 0.f, 0.f, 0.f);
    float4 b = make_float4(0.f, 0.f, 0.f, 0.f);
    float  d = 0.f;

    int i = 0;
    for (; i + 2 <= deg; i += 2) {
        int2 sp = *reinterpret_cast<const int2*>(&lst[i]);
        uint4 v0 = g_xbf[sp.x * 12 + h];
        uint4 v1 = g_xbf[sp.y * 12 + h];

        float x00 = BFLO(v0.x), x01 = BFHI(v0.x);
        float x02 = BFLO(v0.y), x03 = BFHI(v0.y);
        float x04 = BFLO(v0.z), x05 = BFHI(v0.z);
        float x06 = BFLO(v0.w), x07 = BFHI(v0.w);
        float x10 = BFLO(v1.x), x11 = BFHI(v1.x);
        float x12 = BFLO(v1.y), x13 = BFHI(v1.y);
        float x14 = BFLO(v1.z), x15 = BFHI(v1.z);
        float x16 = BFLO(v1.w), x17 = BFHI(v1.w);

        float sc0 = strg
                  + x00*as0.x + x01*as0.y + x02*as0.z + x03*as0.w
                  + x04*as1.x + x05*as1.y + x06*as1.z + x07*as1.w;
        float sc1 = strg
                  + x10*as0.x + x11*as0.y + x12*as0.z + x13*as0.w
                  + x14*as1.x + x15*as1.y + x16*as1.z + x17*as1.w;
        sc0 = (sc0 >= 0.f) ? sc0 : LRELU_SLOPE * sc0;
        sc1 = (sc1 >= 0.f) ? sc1 : LRELU_SLOPE * sc1;
        float w0 = __expf(sc0);
        float w1 = __expf(sc1);

        d += w0 + w1;
        a.x += w0 * x00 + w1 * x10;
        a.y += w0 * x01 + w1 * x11;
        a.z += w0 * x02 + w1 * x12;
        a.w += w0 * x03 + w1 * x13;
        b.x += w0 * x04 + w1 * x14;
        b.y += w0 * x05 + w1 * x15;
        b.z += w0 * x06 + w1 * x16;
        b.w += w0 * x07 + w1 * x17;
    }
    if (i < deg) {
        int s = lst[i];
        uint4 v0 = g_xbf[s * 12 + h];
        float x00 = BFLO(v0.x), x01 = BFHI(v0.x);
        float x02 = BFLO(v0.y), x03 = BFHI(v0.y);
        float x04 = BFLO(v0.z), x05 = BFHI(v0.z);
        float x06 = BFLO(v0.w), x07 = BFHI(v0.w);
        float sc0 = strg
                  + x00*as0.x + x01*as0.y + x02*as0.z + x03*as0.w
                  + x04*as1.x + x05*as1.y + x06*as1.z + x07*as1.w;
        sc0 = (sc0 >= 0.f) ? sc0 : LRELU_SLOPE * sc0;
        float w0 = __expf(sc0);
        d += w0;
        a.x += w0 * x00; a.y += w0 * x01; a.z += w0 * x02; a.w += w0 * x03;
        b.x += w0 * x04; b.y += w0 * x05; b.z += w0 * x06; b.w += w0 * x07;
    }

    float r = __fdividef(1.0f, d + 1e-16f);
    a.x *= r; a.y *= r; a.z *= r; a.w *= r;
    b.x *= r; b.y *= r; b.z *= r; b.w *= r;

    float ss = act ? (a.x*a.x + a.y*a.y + a.z*a.z + a.w*a.w +
                      b.x*b.x + b.y*b.y + b.z*b.z + b.w*b.w) : 0.0f;
    ss += __shfl_xor_sync(0xffffffffu, ss, 8);
    ss += __shfl_xor_sync(0xffffffffu, ss, 4);
    ss += __shfl_xor_sync(0xffffffffu, ss, 2);
    ss += __shfl_xor_sync(0xffffffffu, ss, 1);
    float rms = rsqrtf(ss * (1.0f / 96.0f) + 1e-6f);

    if (act) {
        float4 l0 = reinterpret_cast<const float4*>(lnw)[h * 2];
        float4 l1 = reinterpret_cast<const float4*>(lnw)[h * 2 + 1];
        __nv_bfloat162 w0 = __float22bfloat162_rn(
            make_float2(a.x*rms*l0.x, a.y*rms*l0.y));
        __nv_bfloat162 w1 = __float22bfloat162_rn(
            make_float2(a.z*rms*l0.z, a.w*rms*l0.w));
        __nv_bfloat162 w2 = __float22bfloat162_rn(
            make_float2(b.x*rms*l1.x, b.y*rms*l1.y));
        __nv_bfloat162 w3 = __float22bfloat162_rn(
            make_float2(b.z*rms*l1.z, b.w*rms*l1.w));
        uint4 o;
        o.x = *reinterpret_cast<unsigned*>(&w0);
        o.y = *reinterpret_cast<unsigned*>(&w1);
        o.z = *reinterpret_cast<unsigned*>(&w2);
        o.w = *reinterpret_cast<unsigned*>(&w3);
        g_normbf[n * 12 + h] = o;
    }
}

// ---------------- GEMM via bf16 mma m16n8k16, packed 64-bit fragments ------------
#define PADW 28
#define GEMM_SMEM ((96 + 128) * PADW * 8)
__global__ __launch_bounds__(256) void gemm_mma_kernel(
        const float* __restrict__ x,
        float* __restrict__ out) {
    extern __shared__ uint2 smem2[];
    uint2* Wsm2 = smem2;                  // [96][28]
    uint2* Nsm2 = smem2 + 96 * PADW;      // [128][28]
    unsigned* Wsw = reinterpret_cast<unsigned*>(Wsm2);
    unsigned* Nsw = reinterpret_cast<unsigned*>(Nsm2);

    int tid = threadIdx.x;
    int node0 = blockIdx.x * 128;

    const uint4* wbf4 = reinterpret_cast<const uint4*>(g_wbf);
    for (int i = tid; i < 96 * 12; i += 256) {
        int row = i / 12, j = i - row * 12;
        uint4 v = wbf4[i];
        int ks = j >> 1, half = j & 1;
        int base = (row * PADW + ks * 4) * 2 + half;
        Wsw[base]     = v.x;
        Wsw[base + 2] = v.y;
        Wsw[base + 4] = v.z;
        Wsw[base + 6] = v.w;
    }
    for (int i = tid; i < 128 * 12; i += 256) {
        int mm = i / 12, j = i - mm * 12;
        int node = node0 + mm;
        uint4 v = (node < N_NODES) ? g_normbf[node * 12 + j]
                                   : make_uint4(0u, 0u, 0u, 0u);
        int ks = j >> 1, half = j & 1;
        int base = (mm * PADW + ks * 4) * 2 + half;
        Nsw[base]     = v.x;
        Nsw[base + 2] = v.y;
        Nsw[base + 4] = v.z;
        Nsw[base + 6] = v.w;
    }
    __syncthreads();

    int warp = tid >> 5, lane = tid & 31;
    int m0  = warp * 16;
    int row = lane >> 2;
    int qk  = lane & 3;

    float acc[12][4];
    #pragma unroll
    for (int nt = 0; nt < 12; nt++)
        #pragma unroll
        for (int c = 0; c < 4; c++) acc[nt][c] = 0.0f;

    #pragma unroll
    for (int ks = 0; ks < 6; ks++) {
        uint2 pa0 = Nsm2[(m0 + row)     * PADW + ks * 4 + qk];
        uint2 pa1 = Nsm2[(m0 + row + 8) * PADW + ks * 4 + qk];
        #pragma unroll
        for (int nt = 0; nt < 12; nt++) {
            uint2 pb = Wsm2[(nt * 8 + row) * PADW + ks * 4 + qk];
            asm volatile(
                "mma.sync.aligned.m16n8k16.row.col.f32.bf16.bf16.f32 "
                "{%0,%1,%2,%3}, {%4,%5,%6,%7}, {%8,%9}, {%0,%1,%2,%3};"
                : "+f"(acc[nt][0]), "+f"(acc[nt][1]),
                  "+f"(acc[nt][2]), "+f"(acc[nt][3])
                : "r"(pa0.x), "r"(pa1.x), "r"(pa0.y), "r"(pa1.y),
                  "r"(pb.x), "r"(pb.y));
        }
    }

    int nodeA = node0 + m0 + row;
    int nodeB = nodeA + 8;
    #pragma unroll
    for (int nt = 0; nt < 12; nt++) {
        int col = nt * 8 + qk * 2;
        if (nodeA < N_NODES) {
            float2 xv = *reinterpret_cast<const float2*>(&x[nodeA * 96 + col]);
            float2 ov = make_float2(xv.x + acc[nt][0], xv.y + acc[nt][1]);
            *reinterpret_cast<float2*>(&out[nodeA * 96 + col]) = ov;
        }
        if (nodeB < N_NODES) {
            float2 xv = *reinterpret_cast<const float2*>(&x[nodeB * 96 + col]);
            float2 ov = make_float2(xv.x + acc[nt][2], xv.y + acc[nt][3]);
            *reinterpret_cast<float2*>(&out[nodeB * 96 + col]) = ov;
        }
    }
}

// ---------------- launch -----------------------------------------------------------
extern "C" void kernel_launch(void* const* d_in, const int* in_sizes, int n_in,
                              void* d_out, int out_size) {
    const float* x   = (const float*)d_in[0];
    const void*  ei  = d_in[1];
    const float* w   = (const float*)d_in[2];
    const float* ss  = (const float*)d_in[3];
    const float* st  = (const float*)d_in[4];
    const float* lnw = (const float*)d_in[5];
    float*       out = (float*)d_out;

    static bool attr_set = false;
    if (!attr_set) {
        cudaFuncSetAttribute(gemm_mma_kernel,
                             cudaFuncAttributeMaxDynamicSharedMemorySize,
                             GEMM_SMEM);
        attr_set = true;
    }

    xconv_kernel<<<(N_NODES * 12 + 255) / 256, 256>>>(
        reinterpret_cast<const float4*>(x), (const int*)ei);
    wconv_kernel<<<(96 * 48 + 255) / 256, 256>>>(w);
    place_kernel<<<(E_EDGES + 255) / 256, 256>>>(ei);
    agg_norm_kernel<<<(N_NODES * 16) / 256, 256>>>(
        reinterpret_cast<const float4*>(x), ss, st, lnw);
    gemm_mma_kernel<<<(N_NODES + 127) / 128, 256, GEMM_SMEM>>>(x, out);
}

// round 17
// speedup vs baseline: 1.1162x; 1.0546x over previous
#include <cuda_runtime.h>
#include <cuda_bf16.h>

#define N_NODES 100000
#define E_EDGES 800000
#define H_HEADS 12
#define D_DIM 96
#define LRELU_SLOPE 0.2f
#define SLOTS 64            // per-node bucket capacity (P(deg>64) ~ 1e-40)

// ---------------- scratch ------------------------------------------------------
__device__ int      g_cnt[N_NODES];            // in-degree / cursor
__device__ int      g_srcs[N_NODES * SLOTS];   // bucketed source ids
__device__ uint4    g_normbf[N_NODES * 12];    // normalized rows, bf16x2 words
__device__ unsigned g_wbf[96 * 48];            // W as bf16x2 words
__device__ int      g_is64;

// ---------------- setup: zero counters + dtype detect + W->bf16 ------------------
__global__ void setup_kernel(const int* __restrict__ ei32,
                             const float* __restrict__ wproj) {
    int i = blockIdx.x * blockDim.x + threadIdx.x;
    if (i < N_NODES) g_cnt[i] = 0;
    if (i == 0) {
        int allz = 1;
        #pragma unroll
        for (int k = 1; k < 128; k += 2) allz &= (ei32[k] == 0);
        g_is64 = allz;
    }
    if (i < 96 * 48) {
        float2 v = *reinterpret_cast<const float2*>(&wproj[i * 2]);
        __nv_bfloat162 bv = __float22bfloat162_rn(v);
        g_wbf[i] = *reinterpret_cast<unsigned*>(&bv);
    }
}

// ---------------- place: count + scatter fused -----------------------------------
__global__ void place_kernel(const void* __restrict__ ei) {
    int e = blockIdx.x * blockDim.x + threadIdx.x;
    if (e >= E_EDGES) return;
    int src, trg;
    if (g_is64) {
        const long long* p = (const long long*)ei;
        src = (int)p[e];
        trg = (int)p[E_EDGES + e];
    } else {
        const int* p = (const int*)ei;
        src = p[e];
        trg = p[E_EDGES + e];
    }
    int pos = atomicAdd(&g_cnt[trg], 1);
    if (pos < SLOTS) g_srcs[trg * SLOTS + pos] = src;
}

// ---------------- fused agg: score+exp+agg+normalize+RMS+ln -> bf16 --------------
// ONE WARP per block (2 nodes x 16 lanes): CTA slots churn per-warp, so the
// Poisson degree imbalance no longer strands resources behind slow warps.
__global__ __launch_bounds__(32) void agg_norm_kernel(
        const float4* __restrict__ x4,
        const float*  __restrict__ a_src,
        const float*  __restrict__ a_trg,
        const float*  __restrict__ lnw) {
    int gid = blockIdx.x * 32 + threadIdx.x;    // n*16 + h
    int n = gid >> 4;
    int h = gid & 15;
    bool act = (h < 12);

    float4 as0, as1;
    float strg = 0.0f;
    int deg = 0;
    if (act) {
        as0 = reinterpret_cast<const float4*>(a_src)[h * 2];
        as1 = reinterpret_cast<const float4*>(a_src)[h * 2 + 1];
        float4 at0 = reinterpret_cast<const float4*>(a_trg)[h * 2];
        float4 at1 = reinterpret_cast<const float4*>(a_trg)[h * 2 + 1];
        float4 xn0 = x4[n * 24 + h * 2];
        float4 xn1 = x4[n * 24 + h * 2 + 1];
        strg = xn0.x*at0.x + xn0.y*at0.y + xn0.z*at0.z + xn0.w*at0.w
             + xn1.x*at1.x + xn1.y*at1.y + xn1.z*at1.z + xn1.w*at1.w;
        deg = min(g_cnt[n], SLOTS);
    }
    const int* lst = &g_srcs[n * SLOTS];

    float4 a = make_float4(0.f, 0.f, 0.f, 0.f);
    float4 b = make_float4(0.f, 0.f, 0.f, 0.f);
    float  d = 0.f;

    int i = 0;
    for (; i + 2 <= deg; i += 2) {
        int2 sp = *reinterpret_cast<const int2*>(&lst[i]);
        float4 xa0 = x4[sp.x * 24 + h * 2];
        float4 xb0 = x4[sp.x * 24 + h * 2 + 1];
        float4 xa1 = x4[sp.y * 24 + h * 2];
        float4 xb1 = x4[sp.y * 24 + h * 2 + 1];

        float sc0 = strg
                  + xa0.x*as0.x + xa0.y*as0.y + xa0.z*as0.z + xa0.w*as0.w
                  + xb0.x*as1.x + xb0.y*as1.y + xb0.z*as1.z + xb0.w*as1.w;
        float sc1 = strg
                  + xa1.x*as0.x + xa1.y*as0.y + xa1.z*as0.z + xa1.w*as0.w
                  + xb1.x*as1.x + xb1.y*as1.y + xb1.z*as1.z + xb1.w*as1.w;
        sc0 = (sc0 >= 0.f) ? sc0 : LRELU_SLOPE * sc0;
        sc1 = (sc1 >= 0.f) ? sc1 : LRELU_SLOPE * sc1;
        float w0 = __expf(sc0);
        float w1 = __expf(sc1);

        d += w0 + w1;
        a.x += w0 * xa0.x + w1 * xa1.x;
        a.y += w0 * xa0.y + w1 * xa1.y;
        a.z += w0 * xa0.z + w1 * xa1.z;
        a.w += w0 * xa0.w + w1 * xa1.w;
        b.x += w0 * xb0.x + w1 * xb1.x;
        b.y += w0 * xb0.y + w1 * xb1.y;
        b.z += w0 * xb0.z + w1 * xb1.z;
        b.w += w0 * xb0.w + w1 * xb1.w;
    }
    if (i < deg) {
        int s0 = lst[i];
        float4 xa0 = x4[s0 * 24 + h * 2];
        float4 xb0 = x4[s0 * 24 + h * 2 + 1];
        float sc0 = strg
                  + xa0.x*as0.x + xa0.y*as0.y + xa0.z*as0.z + xa0.w*as0.w
                  + xb0.x*as1.x + xb0.y*as1.y + xb0.z*as1.z + xb0.w*as1.w;
        sc0 = (sc0 >= 0.f) ? sc0 : LRELU_SLOPE * sc0;
        float w0 = __expf(sc0);
        d += w0;
        a.x += w0 * xa0.x; a.y += w0 * xa0.y; a.z += w0 * xa0.z; a.w += w0 * xa0.w;
        b.x += w0 * xb0.x; b.y += w0 * xb0.y; b.z += w0 * xb0.z; b.w += w0 * xb0.w;
    }

    float r = __fdividef(1.0f, d + 1e-16f);
    a.x *= r; a.y *= r; a.z *= r; a.w *= r;
    b.x *= r; b.y *= r; b.z *= r; b.w *= r;

    float ss = act ? (a.x*a.x + a.y*a.y + a.z*a.z + a.w*a.w +
                      b.x*b.x + b.y*b.y + b.z*b.z + b.w*b.w) : 0.0f;
    ss += __shfl_xor_sync(0xffffffffu, ss, 8);
    ss += __shfl_xor_sync(0xffffffffu, ss, 4);
    ss += __shfl_xor_sync(0xffffffffu, ss, 2);
    ss += __shfl_xor_sync(0xffffffffu, ss, 1);
    float rms = rsqrtf(ss * (1.0f / 96.0f) + 1e-6f);

    if (act) {
        float4 l0 = reinterpret_cast<const float4*>(lnw)[h * 2];
        float4 l1 = reinterpret_cast<const float4*>(lnw)[h * 2 + 1];
        __nv_bfloat162 w0 = __float22bfloat162_rn(
            make_float2(a.x*rms*l0.x, a.y*rms*l0.y));
        __nv_bfloat162 w1 = __float22bfloat162_rn(
            make_float2(a.z*rms*l0.z, a.w*rms*l0.w));
        __nv_bfloat162 w2 = __float22bfloat162_rn(
            make_float2(b.x*rms*l1.x, b.y*rms*l1.y));
        __nv_bfloat162 w3 = __float22bfloat162_rn(
            make_float2(b.z*rms*l1.z, b.w*rms*l1.w));
        uint4 o;
        o.x = *reinterpret_cast<unsigned*>(&w0);
        o.y = *reinterpret_cast<unsigned*>(&w1);
        o.z = *reinterpret_cast<unsigned*>(&w2);
        o.w = *reinterpret_cast<unsigned*>(&w3);
        g_normbf[n * 12 + h] = o;
    }
}

// ---------------- GEMM via bf16 mma m16n8k16, packed 64-bit fragments ------------
#define PADW 28
#define GEMM_SMEM ((96 + 128) * PADW * 8)
__global__ __launch_bounds__(256) void gemm_mma_kernel(
        const float* __restrict__ x,
        float* __restrict__ out) {
    extern __shared__ uint2 smem2[];
    uint2* Wsm2 = smem2;                  // [96][28]
    uint2* Nsm2 = smem2 + 96 * PADW;      // [128][28]
    unsigned* Wsw = reinterpret_cast<unsigned*>(Wsm2);
    unsigned* Nsw = reinterpret_cast<unsigned*>(Nsm2);

    int tid = threadIdx.x;
    int node0 = blockIdx.x * 128;

    const uint4* wbf4 = reinterpret_cast<const uint4*>(g_wbf);
    for (int i = tid; i < 96 * 12; i += 256) {
        int row = i / 12, j = i - row * 12;
        uint4 v = wbf4[i];
        int ks = j >> 1, half = j & 1;
        int base = (row * PADW + ks * 4) * 2 + half;
        Wsw[base]     = v.x;
        Wsw[base + 2] = v.y;
        Wsw[base + 4] = v.z;
        Wsw[base + 6] = v.w;
    }
    for (int i = tid; i < 128 * 12; i += 256) {
        int mm = i / 12, j = i - mm * 12;
        int node = node0 + mm;
        uint4 v = (node < N_NODES) ? g_normbf[node * 12 + j]
                                   : make_uint4(0u, 0u, 0u, 0u);
        int ks = j >> 1, half = j & 1;
        int base = (mm * PADW + ks * 4) * 2 + half;
        Nsw[base]     = v.x;
        Nsw[base + 2] = v.y;
        Nsw[base + 4] = v.z;
        Nsw[base + 6] = v.w;
    }
    __syncthreads();

    int warp = tid >> 5, lane = tid & 31;
    int m0  = warp * 16;
    int row = lane >> 2;
    int qk  = lane & 3;

    float acc[12][4];
    #pragma unroll
    for (int nt = 0; nt < 12; nt++)
        #pragma unroll
        for (int c = 0; c < 4; c++) acc[nt][c] = 0.0f;

    #pragma unroll
    for (int ks = 0; ks < 6; ks++) {
        uint2 pa0 = Nsm2[(m0 + row)     * PADW + ks * 4 + qk];
        uint2 pa1 = Nsm2[(m0 + row + 8) * PADW + ks * 4 + qk];
        #pragma unroll
        for (int nt = 0; nt < 12; nt++) {
            uint2 pb = Wsm2[(nt * 8 + row) * PADW + ks * 4 + qk];
            asm volatile(
                "mma.sync.aligned.m16n8k16.row.col.f32.bf16.bf16.f32 "
                "{%0,%1,%2,%3}, {%4,%5,%6,%7}, {%8,%9}, {%0,%1,%2,%3};"
                : "+f"(acc[nt][0]), "+f"(acc[nt][1]),
                  "+f"(acc[nt][2]), "+f"(acc[nt][3])
                : "r"(pa0.x), "r"(pa1.x), "r"(pa0.y), "r"(pa1.y),
                  "r"(pb.x), "r"(pb.y));
        }
    }

    int nodeA = node0 + m0 + row;
    int nodeB = nodeA + 8;
    #pragma unroll
    for (int nt = 0; nt < 12; nt++) {
        int col = nt * 8 + qk * 2;
        if (nodeA < N_NODES) {
            float2 xv = *reinterpret_cast<const float2*>(&x[nodeA * 96 + col]);
            float2 ov = make_float2(xv.x + acc[nt][0], xv.y + acc[nt][1]);
            *reinterpret_cast<float2*>(&out[nodeA * 96 + col]) = ov;
        }
        if (nodeB < N_NODES) {
            float2 xv = *reinterpret_cast<const float2*>(&x[nodeB * 96 + col]);
            float2 ov = make_float2(xv.x + acc[nt][2], xv.y + acc[nt][3]);
            *reinterpret_cast<float2*>(&out[nodeB * 96 + col]) = ov;
        }
    }
}

// ---------------- launch -----------------------------------------------------------
extern "C" void kernel_launch(void* const* d_in, const int* in_sizes, int n_in,
                              void* d_out, int out_size) {
    const float* x   = (const float*)d_in[0];
    const void*  ei  = d_in[1];
    const float* w   = (const float*)d_in[2];
    const float* ss  = (const float*)d_in[3];
    const float* st  = (const float*)d_in[4];
    const float* lnw = (const float*)d_in[5];
    float*       out = (float*)d_out;

    static bool attr_set = false;
    if (!attr_set) {
        cudaFuncSetAttribute(gemm_mma_kernel,
                             cudaFuncAttributeMaxDynamicSharedMemorySize,
                             GEMM_SMEM);
        attr_set = true;
    }

    setup_kernel<<<(N_NODES + 255) / 256, 256>>>((const int*)ei, w);
    place_kernel<<<(E_EDGES + 255) / 256, 256>>>(ei);
    agg_norm_kernel<<<(N_NODES * 16) / 32, 32>>>(
        reinterpret_cast<const float4*>(x), ss, st, lnw);
    gemm_mma_kernel<<<(N_NODES + 127) / 128, 256, GEMM_SMEM>>>(x, out);
}